// round 7
// baseline (speedup 1.0000x reference)
#include <cuda_runtime.h>
#include <math.h>
#include <stdint.h>

#define EE 64
#define SSZ 128
#define FF 640
#define HH 256
#define GG 768          // 3*H
#define LLN 20
#define CC 32
#define BB (EE*SSZ)     // 8192
#define BLM (BB*LLN)    // 163840
#define EPSV 1e-5f

// ---------------- scratch (static __device__, no allocation) ----------------
__device__ float g_x [BB*HH];       // 8 MB
__device__ float g_gi[BB*GG];       // 24 MB
__device__ float g_ha[BB*HH];       // 8 MB  (h ping)
__device__ float g_hb[BB*HH];       // 8 MB  (h pong)
__device__ float g_hs[BLM*HH];      // 160 MB, layout [b][l][h]
__device__ float g_y2[BLM*HH];      // 160 MB
__device__ float g_s1[HH], g_o1[HH];
__device__ float g_s2[HH], g_o2[HH];
__device__ float g_s3[HH], g_o3[HH];
__device__ float g_al[3];

// ---------------- helpers ----------------------------------------------------
__device__ __forceinline__ uint32_t f2tf(float x) {
    uint32_t r;
    asm("cvt.rna.tf32.f32 %0, %1;" : "=r"(r) : "f"(x));
    return r;
}
__device__ __forceinline__ void mma8(float* c, const uint32_t* a, const uint32_t* b) {
    asm volatile("mma.sync.aligned.m16n8k8.row.col.f32.tf32.tf32.f32 "
        "{%0,%1,%2,%3},{%4,%5,%6,%7},{%8,%9},{%0,%1,%2,%3};"
        : "+f"(c[0]), "+f"(c[1]), "+f"(c[2]), "+f"(c[3])
        : "r"(a[0]), "r"(a[1]), "r"(a[2]), "r"(a[3]), "r"(b[0]), "r"(b[1]));
}
__device__ __forceinline__ float sigf(float x) { return 1.f / (1.f + expf(-x)); }

// ---------------- prep ------------------------------------------------------
__global__ void prep_kernel(const float* g1,const float* b1,const float* m1,const float* v1,const float* a1,
                            const float* g2,const float* b2,const float* m2,const float* v2,const float* a2,
                            const float* g3,const float* b3,const float* m3,const float* v3,const float* a3)
{
    int i = threadIdx.x;
    float s;
    s = g1[i] / sqrtf(v1[i] + EPSV); g_s1[i] = s; g_o1[i] = b1[i] - m1[i]*s;
    s = g2[i] / sqrtf(v2[i] + EPSV); g_s2[i] = s; g_o2[i] = b2[i] - m2[i]*s;
    s = g3[i] / sqrtf(v3[i] + EPSV); g_s3[i] = s; g_o3[i] = b3[i] - m3[i]*s;
    if (i == 0) { g_al[0] = a1[0]; g_al[1] = a2[0]; g_al[2] = a3[0]; }
}

__global__ void zero_h_kernel()
{
    int i = blockIdx.x * blockDim.x + threadIdx.x;
    ((float4*)g_ha)[i] = make_float4(0.f, 0.f, 0.f, 0.f);
}

// ---------------- tf32 mma.sync GEMM (unchanged core from R6) ----------------
template<int BM,int BN,int BK,int WM,int WN,int MODE>
__global__ __launch_bounds__(256, 2) void mma_gemm(
    const float* __restrict__ A, const float* __restrict__ W,
    const float* __restrict__ bias, float* __restrict__ Cst,
    int M, int N, int K)
{
    constexpr int BMP = BM + 4, BNP = BN + 4;
    __shared__ uint32_t As[2][BK][BMP];
    __shared__ uint32_t Ws[2][BK][BNP];

    const int tid  = threadIdx.x;
    const int wid  = tid >> 5;
    const int lane = tid & 31;
    const int wm   = wid % WM;
    const int wn   = wid / WM;
    constexpr int WTM = BM / WM;
    constexpr int WTN = BN / WN;
    constexpr int MT  = WTM / 16;
    constexpr int NT  = WTN / 8;

    const int m0 = blockIdx.y * BM;
    const int n0 = blockIdx.x * BN;

    constexpr int KF4  = BK / 4;
    constexpr int NF4A = BM * KF4;
    constexpr int NF4W = BN * KF4;
    constexpr int AIT  = NF4A / 256;
    constexpr int WIT  = (NF4W + 255) / 256;

    const float aA = (MODE == 2) ? g_al[1] : 0.f;
    const int qr = lane >> 2, qc = lane & 3;

    float acc[MT][NT][4];
#pragma unroll
    for (int i = 0; i < MT; i++)
#pragma unroll
        for (int j = 0; j < NT; j++)
#pragma unroll
            for (int q = 0; q < 4; q++) acc[i][j][q] = 0.f;

    const int T = K / BK;

#define LOAD_A_F4(dst, t, it) { \
        int idx = tid + (it)*256; \
        int r = idx >> 2, c = idx & 3; \
        float4 v = *(const float4*)(A + (size_t)(m0 + r) * K + (t)*BK + c*4); \
        if (MODE == 2) { \
            float4 s2 = *(const float4*)(g_s2 + (t)*BK + c*4); \
            float4 o2 = *(const float4*)(g_o2 + (t)*BK + c*4); \
            v.x = fmaf(v.x,s2.x,o2.x); v.x = v.x>=0.f ? v.x : aA*v.x; \
            v.y = fmaf(v.y,s2.y,o2.y); v.y = v.y>=0.f ? v.y : aA*v.y; \
            v.z = fmaf(v.z,s2.z,o2.z); v.z = v.z>=0.f ? v.z : aA*v.z; \
            v.w = fmaf(v.w,s2.w,o2.w); v.w = v.w>=0.f ? v.w : aA*v.w; \
        } \
        dst = v; }
#define STORE_A_F4(buf, v, it) { \
        int idx = tid + (it)*256; \
        int r = idx >> 2, c = idx & 3; \
        As[buf][c*4+0][r] = f2tf(v.x); As[buf][c*4+1][r] = f2tf(v.y); \
        As[buf][c*4+2][r] = f2tf(v.z); As[buf][c*4+3][r] = f2tf(v.w); }
#define LOAD_W_F4(dst, t, it, ok) { \
        int idx = tid + (it)*256; \
        if (ok) { \
            int r = idx >> 2, c = idx & 3; \
            dst = *(const float4*)(W + (size_t)(n0 + r) * K + (t)*BK + c*4); \
        } }
#define STORE_W_F4(buf, v, it, ok) { \
        int idx = tid + (it)*256; \
        if (ok) { \
            int r = idx >> 2, c = idx & 3; \
            Ws[buf][c*4+0][r] = f2tf(v.x); Ws[buf][c*4+1][r] = f2tf(v.y); \
            Ws[buf][c*4+2][r] = f2tf(v.z); Ws[buf][c*4+3][r] = f2tf(v.w); } }

    {
        float4 a[AIT], w[WIT];
#pragma unroll
        for (int it = 0; it < AIT; it++) LOAD_A_F4(a[it], 0, it);
#pragma unroll
        for (int it = 0; it < WIT; it++) {
            bool ok = (NF4W >= 256*(it+1)) || (tid + it*256 < NF4W);
            LOAD_W_F4(w[it], 0, it, ok);
        }
#pragma unroll
        for (int it = 0; it < AIT; it++) STORE_A_F4(0, a[it], it);
#pragma unroll
        for (int it = 0; it < WIT; it++) {
            bool ok = (NF4W >= 256*(it+1)) || (tid + it*256 < NF4W);
            STORE_W_F4(0, w[it], it, ok);
        }
    }
    __syncthreads();

    int buf = 0;
    for (int t = 0; t < T; t++) {
        float4 aP[AIT], wP[WIT];
        if (t + 1 < T) {
#pragma unroll
            for (int it = 0; it < AIT; it++) LOAD_A_F4(aP[it], t+1, it);
#pragma unroll
            for (int it = 0; it < WIT; it++) {
                bool ok = (NF4W >= 256*(it+1)) || (tid + it*256 < NF4W);
                LOAD_W_F4(wP[it], t+1, it, ok);
            }
        }

#pragma unroll
        for (int ks = 0; ks < BK/8; ks++) {
            const int kb = ks * 8;
            uint32_t af[MT][4], bf[NT][2];
#pragma unroll
            for (int mt = 0; mt < MT; mt++) {
                const int m = wm*WTM + mt*16 + qr;
                af[mt][0] = As[buf][kb + qc    ][m];
                af[mt][1] = As[buf][kb + qc    ][m + 8];
                af[mt][2] = As[buf][kb + qc + 4][m];
                af[mt][3] = As[buf][kb + qc + 4][m + 8];
            }
#pragma unroll
            for (int nt = 0; nt < NT; nt++) {
                const int n = wn*WTN + nt*8 + qr;
                bf[nt][0] = Ws[buf][kb + qc    ][n];
                bf[nt][1] = Ws[buf][kb + qc + 4][n];
            }
#pragma unroll
            for (int mt = 0; mt < MT; mt++)
#pragma unroll
                for (int nt = 0; nt < NT; nt++)
                    mma8(acc[mt][nt], af[mt], bf[nt]);
        }

        if (t + 1 < T) {
            const int nb = buf ^ 1;
#pragma unroll
            for (int it = 0; it < AIT; it++) STORE_A_F4(nb, aP[it], it);
#pragma unroll
            for (int it = 0; it < WIT; it++) {
                bool ok = (NF4W >= 256*(it+1)) || (tid + it*256 < NF4W);
                STORE_W_F4(nb, wP[it], it, ok);
            }
            __syncthreads();
            buf = nb;
        }
    }

#pragma unroll
    for (int mt = 0; mt < MT; mt++) {
#pragma unroll
        for (int nt = 0; nt < NT; nt++) {
            const int row = m0 + wm*WTM + mt*16 + qr;
            const int col = n0 + wn*WTN + nt*8 + 2*qc;
            float2 bv = *(const float2*)(bias + col);
            float x0 = acc[mt][nt][0] + bv.x;
            float x1 = acc[mt][nt][1] + bv.y;
            float x2 = acc[mt][nt][2] + bv.x;
            float x3 = acc[mt][nt][3] + bv.y;
            if (MODE == 1 || MODE == 2) {
                const float* sp = (MODE == 1) ? g_s1 : g_s3;
                const float* op = (MODE == 1) ? g_o1 : g_o3;
                const float al  = (MODE == 1) ? g_al[0] : g_al[2];
                float2 sv = *(const float2*)(sp + col);
                float2 ov = *(const float2*)(op + col);
                x0 = fmaf(x0, sv.x, ov.x); x0 = x0>=0.f ? x0 : al*x0;
                x1 = fmaf(x1, sv.y, ov.y); x1 = x1>=0.f ? x1 : al*x1;
                x2 = fmaf(x2, sv.x, ov.x); x2 = x2>=0.f ? x2 : al*x2;
                x3 = fmaf(x3, sv.y, ov.y); x3 = x3>=0.f ? x3 : al*x3;
            }
            *(float2*)(Cst + (size_t)row * N + col)       = make_float2(x0, x1);
            *(float2*)(Cst + (size_t)(row + 8) * N + col) = make_float2(x2, x3);
        }
    }
#undef LOAD_A_F4
#undef STORE_A_F4
#undef LOAD_W_F4
#undef STORE_W_F4
}

// ---------------- fused GRU step: gh GEMM + gate epilogue -------------------
// Tile: 64 batch rows x 64 hidden cols, all 3 gates (acc[3][2][2][4] = 48 regs).
// A = hin[8192,256]; W slabs = W_hh rows g*256+n0..n0+64. Epilogue does the
// full GRU cell update, writing hout (double-buffered) and hs.
__global__ __launch_bounds__(256, 2) void gru_step(
    const float* __restrict__ Whh, const float* __restrict__ bhh,
    const float* __restrict__ hin, float* __restrict__ hout, int l)
{
    constexpr int BMP = 68, BNP = 68;
    __shared__ uint32_t As[2][16][BMP];
    __shared__ uint32_t Ws[2][16][3][BNP];

    const int tid  = threadIdx.x;
    const int wid  = tid >> 5;
    const int lane = tid & 31;
    const int wm   = wid & 1;          // 2 warps along M
    const int wn   = wid >> 1;         // 4 warps along N
    const int qr   = lane >> 2, qc = lane & 3;

    const int m0 = blockIdx.y * 64;
    const int n0 = blockIdx.x * 64;
    const int r  = tid >> 2, c = tid & 3;   // 1 float4/thread per (tile,slab)

    float acc[3][2][2][4];
#pragma unroll
    for (int g = 0; g < 3; g++)
#pragma unroll
        for (int i = 0; i < 2; i++)
#pragma unroll
            for (int j = 0; j < 2; j++)
#pragma unroll
                for (int q = 0; q < 4; q++) acc[g][i][j][q] = 0.f;

    // ---- tile 0 ----
    {
        float4 a = *(const float4*)(hin + (size_t)(m0 + r) * HH + c*4);
        As[0][c*4+0][r] = f2tf(a.x); As[0][c*4+1][r] = f2tf(a.y);
        As[0][c*4+2][r] = f2tf(a.z); As[0][c*4+3][r] = f2tf(a.w);
#pragma unroll
        for (int g = 0; g < 3; g++) {
            float4 w = *(const float4*)(Whh + (size_t)(g*HH + n0 + r) * HH + c*4);
            Ws[0][c*4+0][g][r] = f2tf(w.x); Ws[0][c*4+1][g][r] = f2tf(w.y);
            Ws[0][c*4+2][g][r] = f2tf(w.z); Ws[0][c*4+3][g][r] = f2tf(w.w);
        }
    }
    __syncthreads();

    int buf = 0;
    for (int t = 0; t < 16; t++) {           // K=256, BK=16
        float4 aP, wP[3];
        if (t < 15) {
            aP = *(const float4*)(hin + (size_t)(m0 + r) * HH + (t+1)*16 + c*4);
#pragma unroll
            for (int g = 0; g < 3; g++)
                wP[g] = *(const float4*)(Whh + (size_t)(g*HH + n0 + r) * HH + (t+1)*16 + c*4);
        }

#pragma unroll
        for (int ks = 0; ks < 2; ks++) {
            const int kb = ks * 8;
            uint32_t af[2][4], bf[3][2][2];
#pragma unroll
            for (int mt = 0; mt < 2; mt++) {
                const int m = wm*32 + mt*16 + qr;
                af[mt][0] = As[buf][kb + qc    ][m];
                af[mt][1] = As[buf][kb + qc    ][m + 8];
                af[mt][2] = As[buf][kb + qc + 4][m];
                af[mt][3] = As[buf][kb + qc + 4][m + 8];
            }
#pragma unroll
            for (int g = 0; g < 3; g++)
#pragma unroll
                for (int nt = 0; nt < 2; nt++) {
                    const int n = wn*16 + nt*8 + qr;
                    bf[g][nt][0] = Ws[buf][kb + qc    ][g][n];
                    bf[g][nt][1] = Ws[buf][kb + qc + 4][g][n];
                }
#pragma unroll
            for (int g = 0; g < 3; g++)
#pragma unroll
                for (int mt = 0; mt < 2; mt++)
#pragma unroll
                    for (int nt = 0; nt < 2; nt++)
                        mma8(acc[g][mt][nt], af[mt], bf[g][nt]);
        }

        if (t < 15) {
            const int nb = buf ^ 1;
            As[nb][c*4+0][r] = f2tf(aP.x); As[nb][c*4+1][r] = f2tf(aP.y);
            As[nb][c*4+2][r] = f2tf(aP.z); As[nb][c*4+3][r] = f2tf(aP.w);
#pragma unroll
            for (int g = 0; g < 3; g++) {
                Ws[nb][c*4+0][g][r] = f2tf(wP[g].x); Ws[nb][c*4+1][g][r] = f2tf(wP[g].y);
                Ws[nb][c*4+2][g][r] = f2tf(wP[g].z); Ws[nb][c*4+3][g][r] = f2tf(wP[g].w);
            }
            __syncthreads();
            buf = nb;
        }
    }

    // ---- gate epilogue ----
#pragma unroll
    for (int nt = 0; nt < 2; nt++) {
        const int col = n0 + wn*16 + nt*8 + 2*qc;
        float2 br = *(const float2*)(bhh          + col);
        float2 bz = *(const float2*)(bhh +   HH   + col);
        float2 bn = *(const float2*)(bhh + 2*HH   + col);
#pragma unroll
        for (int mt = 0; mt < 2; mt++) {
#pragma unroll
            for (int h2 = 0; h2 < 2; h2++) {
                const int row = m0 + wm*32 + mt*16 + qr + h2*8;
                const float* gp = g_gi + (size_t)row * GG;
                float2 gr = *(const float2*)(gp          + col);
                float2 gz = *(const float2*)(gp +   HH   + col);
                float2 gn = *(const float2*)(gp + 2*HH   + col);
                float2 ho = *(const float2*)(hin + (size_t)row * HH + col);
                const int q0 = h2 * 2;
                float rr0 = sigf(gr.x + acc[0][mt][nt][q0]   + br.x);
                float rr1 = sigf(gr.y + acc[0][mt][nt][q0+1] + br.y);
                float zz0 = sigf(gz.x + acc[1][mt][nt][q0]   + bz.x);
                float zz1 = sigf(gz.y + acc[1][mt][nt][q0+1] + bz.y);
                float nn0 = tanhf(gn.x + rr0*(acc[2][mt][nt][q0]   + bn.x));
                float nn1 = tanhf(gn.y + rr1*(acc[2][mt][nt][q0+1] + bn.y));
                float hv0 = (1.f - zz0)*nn0 + zz0*ho.x;
                float hv1 = (1.f - zz1)*nn1 + zz1*ho.y;
                *(float2*)(hout + (size_t)row * HH + col) = make_float2(hv0, hv1);
                *(float2*)(g_hs + ((size_t)row * LLN + l) * HH + col) = make_float2(hv0, hv1);
            }
        }
    }
}

// ---------------- launch ----------------------------------------------------
extern "C" void kernel_launch(void* const* d_in, const int* in_sizes, int n_in,
                              void* d_out, int out_size)
{
    const float* A     = (const float*)d_in[0];
    const float* W_lin = (const float*)d_in[1];
    const float* b_lin = (const float*)d_in[2];
    const float* g1    = (const float*)d_in[3];
    const float* be1   = (const float*)d_in[4];
    const float* m1    = (const float*)d_in[5];
    const float* v1    = (const float*)d_in[6];
    const float* a1    = (const float*)d_in[7];
    const float* W_ih  = (const float*)d_in[8];
    const float* W_hh  = (const float*)d_in[9];
    const float* b_ih  = (const float*)d_in[10];
    const float* b_hh  = (const float*)d_in[11];
    const float* g2    = (const float*)d_in[12];
    const float* be2   = (const float*)d_in[13];
    const float* m2    = (const float*)d_in[14];
    const float* v2    = (const float*)d_in[15];
    const float* a2    = (const float*)d_in[16];
    const float* Wc    = (const float*)d_in[17];
    const float* bc    = (const float*)d_in[18];
    const float* g3    = (const float*)d_in[19];
    const float* be3   = (const float*)d_in[20];
    const float* m3    = (const float*)d_in[21];
    const float* v3    = (const float*)d_in[22];
    const float* a3    = (const float*)d_in[23];
    const float* W_mu  = (const float*)d_in[24];
    const float* b_mu  = (const float*)d_in[25];
    float* out = (float*)d_out;

    float *px, *pgi, *pha, *phb, *phs, *py2;
    cudaGetSymbolAddress((void**)&px,  g_x);
    cudaGetSymbolAddress((void**)&pgi, g_gi);
    cudaGetSymbolAddress((void**)&pha, g_ha);
    cudaGetSymbolAddress((void**)&phb, g_hb);
    cudaGetSymbolAddress((void**)&phs, g_hs);
    cudaGetSymbolAddress((void**)&py2, g_y2);

    prep_kernel<<<1, 256>>>(g1, be1, m1, v1, a1, g2, be2, m2, v2, a2, g3, be3, m3, v3, a3);
    zero_h_kernel<<<(BB*HH/4)/256, 256>>>();

    // x = PReLU(BN1(A @ W_lin^T + b_lin)) : [8192,256], K=640
    mma_gemm<128,128,16,4,2,1><<<dim3(HH/128, BB/128), 256>>>(A, W_lin, b_lin, px, BB, HH, FF);

    // gi = x @ W_ih^T + b_ih : [8192,768], K=256
    mma_gemm<128,128,16,4,2,0><<<dim3(GG/128, BB/128), 256>>>(px, W_ih, b_ih, pgi, BB, GG, HH);

    // fused GRU: one kernel per step, ping-pong h buffers
    float* hcur = pha;
    float* hnxt = phb;
    for (int l = 0; l < LLN; l++) {
        gru_step<<<dim3(HH/64, BB/64), 256>>>(W_hh, b_hh, hcur, hnxt, l);
        float* tmp = hcur; hcur = hnxt; hnxt = tmp;
    }

    // y2 = PReLU(BN3(PReLU(BN2(hs)) @ Wc^T + bc)) : [163840,256], K=256
    mma_gemm<128,128,16,4,2,2><<<dim3(HH/128, BLM/128), 256>>>(phs, Wc, bc, py2, BLM, HH, HH);

    // pred = y2 @ W_mu^T + b_mu : [163840,32]
    mma_gemm<128,32,16,4,2,0><<<dim3(1, BLM/128), 256>>>(py2, W_mu, b_mu, out, BLM, CC, HH);
}

// round 9
// speedup vs baseline: 1.7302x; 1.7302x over previous
#include <cuda_runtime.h>
#include <cuda_fp16.h>
#include <math.h>
#include <stdint.h>

#define EE 64
#define SSZ 128
#define FF 640
#define HH 256
#define GG 768          // 3*H
#define LLN 20
#define CC 32
#define BB (EE*SSZ)     // 8192
#define BLM (BB*LLN)    // 163840
#define EPSV 1e-5f

// ---------------- scratch (static __device__, no allocation) ----------------
__device__ float g_x [BB*HH];       // 8 MB
__device__ float g_gi[BB*GG];       // 24 MB
__device__ float g_h [BB*HH];       // 8 MB
__device__ float g_gh[BB*GG];       // 24 MB
__device__ float g_hs[BLM*HH];      // 160 MB, layout [b][l][h]
__device__ float g_y2[BLM*HH];      // 160 MB
__device__ float g_s1[HH], g_o1[HH];
__device__ float g_s2[HH], g_o2[HH];
__device__ float g_s3[HH], g_o3[HH];
__device__ float g_al[3];

// ---------------- helpers ----------------------------------------------------
__device__ __forceinline__ uint32_t pk2(float a, float b) {
    __half2 h = __floats2half2_rn(a, b);
    return *(uint32_t*)&h;
}
__device__ __forceinline__ uint32_t cvta_s(const void* p) {
    return (uint32_t)__cvta_generic_to_shared(p);
}
__device__ __forceinline__ void mma16(float* c, const uint32_t* a, const uint32_t* b) {
    asm volatile("mma.sync.aligned.m16n8k16.row.col.f32.f16.f16.f32 "
        "{%0,%1,%2,%3},{%4,%5,%6,%7},{%8,%9},{%0,%1,%2,%3};"
        : "+f"(c[0]), "+f"(c[1]), "+f"(c[2]), "+f"(c[3])
        : "r"(a[0]), "r"(a[1]), "r"(a[2]), "r"(a[3]), "r"(b[0]), "r"(b[1]));
}
#define LDSM4(r0,r1,r2,r3,addr) \
    asm volatile("ldmatrix.sync.aligned.m8n8.x4.shared.b16 {%0,%1,%2,%3}, [%4];" \
        : "=r"(r0),"=r"(r1),"=r"(r2),"=r"(r3) : "r"(addr))

__device__ __forceinline__ float sigf(float x) { return 1.f / (1.f + expf(-x)); }

// ---------------- prep ------------------------------------------------------
__global__ void prep_kernel(const float* g1,const float* b1,const float* m1,const float* v1,const float* a1,
                            const float* g2,const float* b2,const float* m2,const float* v2,const float* a2,
                            const float* g3,const float* b3,const float* m3,const float* v3,const float* a3)
{
    int i = threadIdx.x;
    float s;
    s = g1[i] / sqrtf(v1[i] + EPSV); g_s1[i] = s; g_o1[i] = b1[i] - m1[i]*s;
    s = g2[i] / sqrtf(v2[i] + EPSV); g_s2[i] = s; g_o2[i] = b2[i] - m2[i]*s;
    s = g3[i] / sqrtf(v3[i] + EPSV); g_s3[i] = s; g_o3[i] = b3[i] - m3[i]*s;
    if (i == 0) { g_al[0] = a1[0]; g_al[1] = a2[0]; g_al[2] = a3[0]; }
}

__global__ void zero_h_kernel()
{
    int i = blockIdx.x * blockDim.x + threadIdx.x;
    ((float4*)g_h)[i] = make_float4(0.f, 0.f, 0.f, 0.f);
}

// ---------------- fp16 mma.sync GEMM with ldmatrix ---------------------------
// C = epi(A @ W^T + bias). A:[M,K], W:[N,K] row-major fp32, converted to fp16
// on the STS path. BK=32; row pitch 40 halfs (80B) -> ldmatrix conflict-free.
// B fragments via NON-trans ldmatrix on n-rows ([n][k] smem is col-major B).
// MODE 0: bias. MODE 1: bias+BN1+PReLU. MODE 2: BN2+PReLU on A load,
// bias+BN3+PReLU epilogue.
template<int BM,int BN,int WM,int WN,int MODE>
__global__ __launch_bounds__(256, 2) void hgemm(
    const float* __restrict__ A, const float* __restrict__ W,
    const float* __restrict__ bias, float* __restrict__ Cst,
    int M, int N, int K)
{
    constexpr int BK   = 32;
    constexpr int PIT  = 40;                  // padded row pitch in halfs
    __shared__ __align__(16) __half Ah[2][BM*PIT];
    __shared__ __align__(16) __half Wh[2][BN*PIT];

    const int tid  = threadIdx.x;
    const int wid  = tid >> 5;
    const int lane = tid & 31;
    const int wm   = wid % WM;
    const int wn   = wid / WM;
    constexpr int WTM = BM / WM;
    constexpr int WTN = BN / WN;
    constexpr int MT  = WTM / 16;
    constexpr int NT  = WTN / 8;              // even
    const int qr = lane >> 2, qc = lane & 3;
    const int l8 = lane & 7;

    const int m0 = blockIdx.y * BM;
    const int n0 = blockIdx.x * BN;

    constexpr int ACH = BM * 4;               // 16B chunks per A tile
    constexpr int WCH = BN * 4;
    constexpr int AIT = ACH / 256;            // 2 for BM=128
    constexpr int WIT = (WCH + 255) / 256;

    const float aA = (MODE == 2) ? g_al[1] : 0.f;

    float acc[MT][NT][4];
#pragma unroll
    for (int i = 0; i < MT; i++)
#pragma unroll
        for (int j = 0; j < NT; j++)
#pragma unroll
            for (int q = 0; q < 4; q++) acc[i][j][q] = 0.f;

    const int T = K / BK;

#define LOAD_A_CH(dst, t, it) { \
        int idx = tid + (it)*256; \
        int r = idx >> 2, c = idx & 3; \
        const float* p = A + (size_t)(m0 + r) * K + (t)*BK + c*8; \
        float4 v0 = *(const float4*)p; \
        float4 v1 = *(const float4*)(p + 4); \
        if (MODE == 2) { \
            int kk = (t)*BK + c*8; \
            float4 s0 = *(const float4*)(g_s2 + kk),  s1 = *(const float4*)(g_s2 + kk + 4); \
            float4 o0 = *(const float4*)(g_o2 + kk),  o1 = *(const float4*)(g_o2 + kk + 4); \
            v0.x = fmaf(v0.x,s0.x,o0.x); v0.x = v0.x>=0.f ? v0.x : aA*v0.x; \
            v0.y = fmaf(v0.y,s0.y,o0.y); v0.y = v0.y>=0.f ? v0.y : aA*v0.y; \
            v0.z = fmaf(v0.z,s0.z,o0.z); v0.z = v0.z>=0.f ? v0.z : aA*v0.z; \
            v0.w = fmaf(v0.w,s0.w,o0.w); v0.w = v0.w>=0.f ? v0.w : aA*v0.w; \
            v1.x = fmaf(v1.x,s1.x,o1.x); v1.x = v1.x>=0.f ? v1.x : aA*v1.x; \
            v1.y = fmaf(v1.y,s1.y,o1.y); v1.y = v1.y>=0.f ? v1.y : aA*v1.y; \
            v1.z = fmaf(v1.z,s1.z,o1.z); v1.z = v1.z>=0.f ? v1.z : aA*v1.z; \
            v1.w = fmaf(v1.w,s1.w,o1.w); v1.w = v1.w>=0.f ? v1.w : aA*v1.w; \
        } \
        dst = make_uint4(pk2(v0.x,v0.y), pk2(v0.z,v0.w), pk2(v1.x,v1.y), pk2(v1.z,v1.w)); }
#define STORE_A_CH(buf, v, it) { \
        int idx = tid + (it)*256; \
        int r = idx >> 2, c = idx & 3; \
        *(uint4*)&Ah[buf][r*PIT + c*8] = v; }
#define LOAD_W_CH(dst, t, it, ok) { \
        int idx = tid + (it)*256; \
        if (ok) { \
            int r = idx >> 2, c = idx & 3; \
            const float* p = W + (size_t)(n0 + r) * K + (t)*BK + c*8; \
            float4 v0 = *(const float4*)p; \
            float4 v1 = *(const float4*)(p + 4); \
            dst = make_uint4(pk2(v0.x,v0.y), pk2(v0.z,v0.w), pk2(v1.x,v1.y), pk2(v1.z,v1.w)); } }
#define STORE_W_CH(buf, v, it, ok) { \
        int idx = tid + (it)*256; \
        if (ok) { \
            int r = idx >> 2, c = idx & 3; \
            *(uint4*)&Wh[buf][r*PIT + c*8] = v; } }

    {   // tile 0
        uint4 a[AIT], w[WIT];
#pragma unroll
        for (int it = 0; it < AIT; it++) LOAD_A_CH(a[it], 0, it);
#pragma unroll
        for (int it = 0; it < WIT; it++) {
            bool ok = (WCH >= 256*(it+1)) || (tid + it*256 < WCH);
            LOAD_W_CH(w[it], 0, it, ok);
        }
#pragma unroll
        for (int it = 0; it < AIT; it++) STORE_A_CH(0, a[it], it);
#pragma unroll
        for (int it = 0; it < WIT; it++) {
            bool ok = (WCH >= 256*(it+1)) || (tid + it*256 < WCH);
            STORE_W_CH(0, w[it], it, ok);
        }
    }
    __syncthreads();

    int buf = 0;
    for (int t = 0; t < T; t++) {
        uint4 aP[AIT], wP[WIT];
        if (t + 1 < T) {
#pragma unroll
            for (int it = 0; it < AIT; it++) LOAD_A_CH(aP[it], t+1, it);
#pragma unroll
            for (int it = 0; it < WIT; it++) {
                bool ok = (WCH >= 256*(it+1)) || (tid + it*256 < WCH);
                LOAD_W_CH(wP[it], t+1, it, ok);
            }
        }

#pragma unroll
        for (int ks = 0; ks < 2; ks++) {          // two k16 steps per BK=32
            uint32_t af[MT][4], bf[NT][2];
#pragma unroll
            for (int mt = 0; mt < MT; mt++) {
                // mat0: m0-7 k-lo | mat1: m8-15 k-lo | mat2: m0-7 k-hi | mat3: m8-15 k-hi
                const int m  = wm*WTM + mt*16 + l8 + ((lane >> 3) & 1) * 8;
                const int ck = 2*ks + (lane >> 4);
                uint32_t ad = cvta_s(&Ah[buf][m*PIT + ck*8]);
                LDSM4(af[mt][0], af[mt][1], af[mt][2], af[mt][3], ad);
            }
#pragma unroll
            for (int np = 0; np < NT/2; np++) {
                // mat0: n0-7 k-lo | mat1: n0-7 k-hi | mat2: n8-15 k-lo | mat3: n8-15 k-hi
                // NON-trans: [n][k] smem rows are B columns (col-major B).
                const int n  = wn*WTN + np*16 + l8 + ((lane >> 4) & 1) * 8;
                const int ck = 2*ks + ((lane >> 3) & 1);
                uint32_t bd = cvta_s(&Wh[buf][n*PIT + ck*8]);
                LDSM4(bf[2*np][0], bf[2*np][1], bf[2*np+1][0], bf[2*np+1][1], bd);
            }
#pragma unroll
            for (int mt = 0; mt < MT; mt++)
#pragma unroll
                for (int nt = 0; nt < NT; nt++)
                    mma16(acc[mt][nt], af[mt], bf[nt]);
        }

        if (t + 1 < T) {
            const int nb = buf ^ 1;
#pragma unroll
            for (int it = 0; it < AIT; it++) STORE_A_CH(nb, aP[it], it);
#pragma unroll
            for (int it = 0; it < WIT; it++) {
                bool ok = (WCH >= 256*(it+1)) || (tid + it*256 < WCH);
                STORE_W_CH(nb, wP[it], it, ok);
            }
            __syncthreads();
            buf = nb;
        }
    }

    // ---- epilogue ----
#pragma unroll
    for (int mt = 0; mt < MT; mt++) {
#pragma unroll
        for (int nt = 0; nt < NT; nt++) {
            const int row = m0 + wm*WTM + mt*16 + qr;
            const int col = n0 + wn*WTN + nt*8 + 2*qc;
            float2 bv = *(const float2*)(bias + col);
            float x0 = acc[mt][nt][0] + bv.x;
            float x1 = acc[mt][nt][1] + bv.y;
            float x2 = acc[mt][nt][2] + bv.x;
            float x3 = acc[mt][nt][3] + bv.y;
            if (MODE == 1 || MODE == 2) {
                const float* sp = (MODE == 1) ? g_s1 : g_s3;
                const float* op = (MODE == 1) ? g_o1 : g_o3;
                const float al  = (MODE == 1) ? g_al[0] : g_al[2];
                float2 sv = *(const float2*)(sp + col);
                float2 ov = *(const float2*)(op + col);
                x0 = fmaf(x0, sv.x, ov.x); x0 = x0>=0.f ? x0 : al*x0;
                x1 = fmaf(x1, sv.y, ov.y); x1 = x1>=0.f ? x1 : al*x1;
                x2 = fmaf(x2, sv.x, ov.x); x2 = x2>=0.f ? x2 : al*x2;
                x3 = fmaf(x3, sv.y, ov.y); x3 = x3>=0.f ? x3 : al*x3;
            }
            *(float2*)(Cst + (size_t)row * N + col)       = make_float2(x0, x1);
            *(float2*)(Cst + (size_t)(row + 8) * N + col) = make_float2(x2, x3);
        }
    }
#undef LOAD_A_CH
#undef STORE_A_CH
#undef LOAD_W_CH
#undef STORE_W_CH
}

// ---------------- GRU gate elementwise step ---------------------------------
__global__ void gate_kernel(int l)
{
    int idx = blockIdx.x * blockDim.x + threadIdx.x;   // over BB*HH/4
    int j4 = idx % (HH/4);
    int b  = idx / (HH/4);
    int base = b * (GG/4);

    float4 gir = ((const float4*)g_gi)[base            + j4];
    float4 giz = ((const float4*)g_gi)[base +   HH/4   + j4];
    float4 gin = ((const float4*)g_gi)[base + 2*(HH/4) + j4];
    float4 ghr = ((const float4*)g_gh)[base            + j4];
    float4 ghz = ((const float4*)g_gh)[base +   HH/4   + j4];
    float4 ghn = ((const float4*)g_gh)[base + 2*(HH/4) + j4];
    float4 h   = ((const float4*)g_h )[b*(HH/4) + j4];

    float r, z, n;
    r = sigf(gir.x + ghr.x); z = sigf(giz.x + ghz.x);
    n = tanhf(gin.x + r*ghn.x); h.x = (1.f - z)*n + z*h.x;
    r = sigf(gir.y + ghr.y); z = sigf(giz.y + ghz.y);
    n = tanhf(gin.y + r*ghn.y); h.y = (1.f - z)*n + z*h.y;
    r = sigf(gir.z + ghr.z); z = sigf(giz.z + ghz.z);
    n = tanhf(gin.z + r*ghn.z); h.z = (1.f - z)*n + z*h.z;
    r = sigf(gir.w + ghr.w); z = sigf(giz.w + ghz.w);
    n = tanhf(gin.w + r*ghn.w); h.w = (1.f - z)*n + z*h.w;

    ((float4*)g_h)[b*(HH/4) + j4] = h;
    ((float4*)g_hs)[((size_t)b*LLN + l)*(HH/4) + j4] = h;
}

// ---------------- launch ----------------------------------------------------
extern "C" void kernel_launch(void* const* d_in, const int* in_sizes, int n_in,
                              void* d_out, int out_size)
{
    const float* A     = (const float*)d_in[0];
    const float* W_lin = (const float*)d_in[1];
    const float* b_lin = (const float*)d_in[2];
    const float* g1    = (const float*)d_in[3];
    const float* be1   = (const float*)d_in[4];
    const float* m1    = (const float*)d_in[5];
    const float* v1    = (const float*)d_in[6];
    const float* a1    = (const float*)d_in[7];
    const float* W_ih  = (const float*)d_in[8];
    const float* W_hh  = (const float*)d_in[9];
    const float* b_ih  = (const float*)d_in[10];
    const float* b_hh  = (const float*)d_in[11];
    const float* g2    = (const float*)d_in[12];
    const float* be2   = (const float*)d_in[13];
    const float* m2    = (const float*)d_in[14];
    const float* v2    = (const float*)d_in[15];
    const float* a2    = (const float*)d_in[16];
    const float* Wc    = (const float*)d_in[17];
    const float* bc    = (const float*)d_in[18];
    const float* g3    = (const float*)d_in[19];
    const float* be3   = (const float*)d_in[20];
    const float* m3    = (const float*)d_in[21];
    const float* v3    = (const float*)d_in[22];
    const float* a3    = (const float*)d_in[23];
    const float* W_mu  = (const float*)d_in[24];
    const float* b_mu  = (const float*)d_in[25];
    float* out = (float*)d_out;

    float *px, *pgi, *ph, *pgh, *phs, *py2;
    cudaGetSymbolAddress((void**)&px,  g_x);
    cudaGetSymbolAddress((void**)&pgi, g_gi);
    cudaGetSymbolAddress((void**)&ph,  g_h);
    cudaGetSymbolAddress((void**)&pgh, g_gh);
    cudaGetSymbolAddress((void**)&phs, g_hs);
    cudaGetSymbolAddress((void**)&py2, g_y2);

    prep_kernel<<<1, 256>>>(g1, be1, m1, v1, a1, g2, be2, m2, v2, a2, g3, be3, m3, v3, a3);
    zero_h_kernel<<<(BB*HH/4)/256, 256>>>();

    // x = PReLU(BN1(A @ W_lin^T + b_lin)) : [8192,256], K=640
    hgemm<128,128,4,2,1><<<dim3(HH/128, BB/128), 256>>>(A, W_lin, b_lin, px, BB, HH, FF);

    // gi = x @ W_ih^T + b_ih : [8192,768], K=256
    hgemm<128,128,4,2,0><<<dim3(GG/128, BB/128), 256>>>(px, W_ih, b_ih, pgi, BB, GG, HH);

    // GRU recurrence
    for (int l = 0; l < LLN; l++) {
        hgemm<128,128,4,2,0><<<dim3(GG/128, BB/128), 256>>>(ph, W_hh, b_hh, pgh, BB, GG, HH);
        gate_kernel<<<(BB*HH/4)/256, 256>>>(l);
    }

    // y2 = PReLU(BN3(PReLU(BN2(hs)) @ Wc^T + bc)) : [163840,256], K=256
    hgemm<128,128,4,2,2><<<dim3(HH/128, BLM/128), 256>>>(phs, Wc, bc, py2, BLM, HH, HH);

    // pred = y2 @ W_mu^T + b_mu : [163840,32]
    hgemm<128,32,4,2,0><<<dim3(1, BLM/128), 256>>>(py2, W_mu, b_mu, out, BLM, CC, HH);
}